// round 10
// baseline (speedup 1.0000x reference)
#include <cuda_runtime.h>
#include <cuda_fp16.h>
#include <stdint.h>

#define MAX_NODES 100000
#define IN_CH 128
#define HID 16
#define OUT_CH 32
#define CAP 128

__device__ __align__(16) int    g_cnt[MAX_NODES];          // zero at load; re-zeroed in agg2 epilogue
__device__ __align__(16) float  g_dis[MAX_NODES];
__device__ __align__(16) int    g_eidx[MAX_NODES * CAP];   // ELL: src ids grouped by dst
__device__ __align__(16) __half g_h1[MAX_NODES * HID];     // (x@W1)*dis[n]  (fp16 rows, 32B)
__device__ __align__(16) __half g_hr[MAX_NODES * HID];     // relu(dis*agg+b1)*dis[n]

// ---------------------------------------------------------------- ELL fill: 4 edges per thread
__global__ void k_fill(const int* __restrict__ ei, int E) {
    // per-warp dtype sniff on first 128 logical elements' high words (L1 broadcast)
    int lane = threadIdx.x & 31;
    int o = 0;
#pragma unroll
    for (int q = 0; q < 4; q++) o |= __ldg(&ei[2 * (lane * 4 + q) + 1]);
    int is64 = __any_sync(0xffffffffu, o != 0) ? 0 : 1;

    int t = blockIdx.x * blockDim.x + threadIdx.x;
    int e0 = t * 4;
    if (e0 >= E) return;

    int s[4], d[4];
    if (is64) {
        int4 a = __ldg((const int4*)(ei + 2 * e0));
        int4 b = __ldg((const int4*)(ei + 2 * e0) + 1);
        s[0] = a.x; s[1] = a.z; s[2] = b.x; s[3] = b.z;
        int4 c = __ldg((const int4*)(ei + 2 * (size_t)E + 2 * e0));
        int4 f = __ldg((const int4*)(ei + 2 * (size_t)E + 2 * e0) + 1);
        d[0] = c.x; d[1] = c.z; d[2] = f.x; d[3] = f.z;
    } else {
        int4 a = __ldg((const int4*)(ei + e0));
        s[0] = a.x; s[1] = a.y; s[2] = a.z; s[3] = a.w;
        int4 c = __ldg((const int4*)(ei + E + e0));
        d[0] = c.x; d[1] = c.y; d[2] = c.z; d[3] = c.w;
    }
#pragma unroll
    for (int k = 0; k < 4; k++) {
        if (e0 + k < E) {
            int c = atomicAdd(&g_cnt[d[k]], 1);
            if (c < CAP) g_eidx[(d[k] << 7) + c] = s[k];
        }
    }
}

// ---------------------------------------------------------------- GEMM1 (+dis): h1 = (x@W1)*dis, fp16
__global__ void k_gemm1(const float* __restrict__ x, const float* __restrict__ W1, int n) {
    int lane  = threadIdx.x & 31;
    int warp0 = (blockIdx.x * blockDim.x + threadIdx.x) >> 5;
    int nw    = (gridDim.x * blockDim.x) >> 5;

    float w[4][16];
#pragma unroll
    for (int j = 0; j < 4; j++)
#pragma unroll
        for (int c = 0; c < 16; c++) w[j][c] = W1[(lane * 4 + j) * HID + c];

    // value-split butterfly leaves lane L holding channel bitrev4(L&15)
    int cmap = ((lane & 1) << 3) | ((lane & 2) << 1) | ((lane & 4) >> 1) | ((lane & 8) >> 3);

    for (int node = warp0; node < n; node += nw) {
        float4 v = __ldg(((const float4*)(x + (size_t)node * IN_CH)) + lane);
        float acc[16];
#pragma unroll
        for (int c = 0; c < 16; c++)
            acc[c] = v.x * w[0][c] + v.y * w[1][c] + v.z * w[2][c] + v.w * w[3][c];

#pragma unroll
        for (int step = 0; step < 4; step++) {
            int half = 8 >> step;
            bool up = (lane >> step) & 1;
#pragma unroll
            for (int j = 0; j < 8; j++) {
                if (j < half) {
                    float send = up ? acc[j] : acc[j + half];
                    float recv = __shfl_xor_sync(0xffffffffu, send, 1 << step);
                    acc[j] = (up ? acc[j + half] : acc[j]) + recv;
                }
            }
        }
        float tot = acc[0] + __shfl_xor_sync(0xffffffffu, acc[0], 16);
        float dn = rsqrtf((float)(__ldg(&g_cnt[node]) + 1));
        if (lane == 0) g_dis[node] = dn;
        float mine = tot * dn;
        float partner = __shfl_xor_sync(0xffffffffu, mine, 8);
        if (lane < 8) {
            __half2 p = __floats2half2_rn(mine, partner);
            *(__half2*)&g_h1[(size_t)node * HID + cmap] = p;   // cmap even for lane<8
        }
    }
}

// ---------------------------------------------------------------- layer-1 aggregation + ReLU
// Warp per node; lane owns channel quad j=lane&3 of 4 edges (g=lane>>2); int4 index loads; predicated.
__global__ void k_agg1(const float* __restrict__ b1, int n) {
    int node = (blockIdx.x * blockDim.x + threadIdx.x) >> 5;
    if (node >= n) return;
    int lane = threadIdx.x & 31;
    int j = lane & 3;
    int g = lane >> 2;
    int end = min(g_cnt[node], CAP);
    const int4* idx4 = (const int4*)(g_eidx + (node << 7));

    float ax = 0.f, ay = 0.f, az = 0.f, aw = 0.f;
    int iters = (end + 31) >> 5;
#pragma unroll 1
    for (int it = 0; it < iters; it++) {
        int4 q = __ldg(idx4 + it * 8 + g);
        int base = (it << 5) + (g << 2);
#pragma unroll
        for (int k = 0; k < 4; k++) {
            int s = (k == 0) ? q.x : (k == 1) ? q.y : (k == 2) ? q.z : q.w;
            if (base + k < end) {
                uint2 r = __ldg((const uint2*)(g_h1 + (size_t)s * HID) + j);
                float2 fa = __half22float2(*(__half2*)&r.x);
                float2 fb = __half22float2(*(__half2*)&r.y);
                ax += fa.x; ay += fa.y; az += fb.x; aw += fb.y;
            }
        }
    }
#pragma unroll
    for (int m = 4; m <= 16; m <<= 1) {
        ax += __shfl_xor_sync(0xffffffffu, ax, m);
        ay += __shfl_xor_sync(0xffffffffu, ay, m);
        az += __shfl_xor_sync(0xffffffffu, az, m);
        aw += __shfl_xor_sync(0xffffffffu, aw, m);
    }
    if (lane < 4) {
        float dn = g_dis[node];
        uint2 sr = *((const uint2*)(g_h1 + (size_t)node * HID) + j);
        float2 sa = __half22float2(*(__half2*)&sr.x), sb = __half22float2(*(__half2*)&sr.y);
        float4 bb = *(const float4*)&b1[4 * j];
        float ox = fmaxf(dn * (ax + sa.x) + bb.x, 0.0f) * dn;
        float oy = fmaxf(dn * (ay + sa.y) + bb.y, 0.0f) * dn;
        float oz = fmaxf(dn * (az + sb.x) + bb.z, 0.0f) * dn;
        float ow = fmaxf(dn * (aw + sb.y) + bb.w, 0.0f) * dn;
        uint2 o;
        *(__half2*)&o.x = __floats2half2_rn(ox, oy);
        *(__half2*)&o.y = __floats2half2_rn(oz, ow);
        *((uint2*)(g_hr + (size_t)node * HID) + j) = o;
    }
}

// ---------------------------------------------------------------- layer-2 aggregation + W2 -> out (+cnt reset)
__global__ void k_agg2(const float* __restrict__ W2, const float* __restrict__ b2,
                       float* __restrict__ out, int n) {
    int node = (blockIdx.x * blockDim.x + threadIdx.x) >> 5;
    if (node >= n) return;
    int lane = threadIdx.x & 31;
    int j = lane & 3;
    int g = lane >> 2;

    float w2c[16];
#pragma unroll
    for (int c = 0; c < 16; c++) w2c[c] = __ldg(&W2[c * OUT_CH + lane]);
    float bb = __ldg(&b2[lane]);

    int end = min(g_cnt[node], CAP);
    const int4* idx4 = (const int4*)(g_eidx + (node << 7));

    float ax = 0.f, ay = 0.f, az = 0.f, aw = 0.f;
    int iters = (end + 31) >> 5;
#pragma unroll 1
    for (int it = 0; it < iters; it++) {
        int4 q = __ldg(idx4 + it * 8 + g);
        int base = (it << 5) + (g << 2);
#pragma unroll
        for (int k = 0; k < 4; k++) {
            int s = (k == 0) ? q.x : (k == 1) ? q.y : (k == 2) ? q.z : q.w;
            if (base + k < end) {
                uint2 r = __ldg((const uint2*)(g_hr + (size_t)s * HID) + j);
                float2 fa = __half22float2(*(__half2*)&r.x);
                float2 fb = __half22float2(*(__half2*)&r.y);
                ax += fa.x; ay += fa.y; az += fb.x; aw += fb.y;
            }
        }
    }
    if (g == 0) {   // add self once, pre-reduction (lanes 0..3)
        uint2 sr = *((const uint2*)(g_hr + (size_t)node * HID) + j);
        float2 sa = __half22float2(*(__half2*)&sr.x), sb = __half22float2(*(__half2*)&sr.y);
        ax += sa.x; ay += sa.y; az += sb.x; aw += sb.y;
    }
#pragma unroll
    for (int m = 4; m <= 16; m <<= 1) {
        ax += __shfl_xor_sync(0xffffffffu, ax, m);
        ay += __shfl_xor_sync(0xffffffffu, ay, m);
        az += __shfl_xor_sync(0xffffffffu, az, m);
        aw += __shfl_xor_sync(0xffffffffu, aw, m);
    }
    float s = 0.0f;
#pragma unroll
    for (int jj = 0; jj < 4; jj++) {
        float tx = __shfl_sync(0xffffffffu, ax, jj);
        float ty = __shfl_sync(0xffffffffu, ay, jj);
        float tz = __shfl_sync(0xffffffffu, az, jj);
        float tw = __shfl_sync(0xffffffffu, aw, jj);
        s = fmaf(tx, w2c[4 * jj + 0], s);
        s = fmaf(ty, w2c[4 * jj + 1], s);
        s = fmaf(tz, w2c[4 * jj + 2], s);
        s = fmaf(tw, w2c[4 * jj + 3], s);
    }
    float dn = g_dis[node];
    out[(size_t)node * OUT_CH + lane] = bb + dn * s;
    if (lane == 0) g_cnt[node] = 0;     // reset for next call (deterministic per call)
}

// ----------------------------------------------------------------
extern "C" void kernel_launch(void* const* d_in, const int* in_sizes, int n_in,
                              void* d_out, int out_size) {
    const float* x   = (const float*)d_in[0];
    const int*   ei  = (const int*)d_in[1];
    const float* W1  = (const float*)d_in[2];
    const float* b1  = (const float*)d_in[3];
    const float* W2  = (const float*)d_in[4];
    const float* b2  = (const float*)d_in[5];
    float*       out = (float*)d_out;

    const int N = in_sizes[0] / IN_CH;
    const int E = in_sizes[1] / 2;
    const int TB = 256;

    k_fill<<<(E / 4 + TB - 1) / TB, TB>>>(ei, E);           // 1
    k_gemm1<<<1024, TB>>>(x, W1, N);                        // 2
    k_agg1<<<(N * 32 + TB - 1) / TB, TB>>>(b1, N);          // 3
    k_agg2<<<(N * 32 + TB - 1) / TB, TB>>>(W2, b2, out, N); // 4  <- profiled window
}

// round 11
// speedup vs baseline: 1.0100x; 1.0100x over previous
#include <cuda_runtime.h>
#include <cuda_fp16.h>
#include <stdint.h>

#define MAX_NODES 100000
#define IN_CH 128
#define HID 16
#define OUT_CH 32
#define CAP 128

__device__ __align__(16) int    g_cnt[MAX_NODES];          // zero at load; re-zeroed in agg2 epilogue
__device__ __align__(16) float  g_dis[MAX_NODES];
__device__ __align__(16) int    g_eidx[MAX_NODES * CAP];   // ELL: src ids grouped by dst
__device__ __align__(16) __half g_h1[MAX_NODES * HID];     // (x@W1)*dis[n]  (fp16 rows, 32B)
__device__ __align__(16) __half g_hr[MAX_NODES * HID];     // relu(dis*agg+b1)*dis[n]

// ---------------------------------------------------------------- ELL fill: 4 edges per thread
__global__ void k_fill(const int* __restrict__ ei, int E) {
    // per-warp dtype sniff on first 128 logical elements' high words (L1 broadcast)
    int lane = threadIdx.x & 31;
    int o = 0;
#pragma unroll
    for (int q = 0; q < 4; q++) o |= __ldg(&ei[2 * (lane * 4 + q) + 1]);
    int is64 = __any_sync(0xffffffffu, o != 0) ? 0 : 1;

    int t = blockIdx.x * blockDim.x + threadIdx.x;
    int e0 = t * 4;
    if (e0 >= E) return;

    int s[4], d[4];
    if (is64) {
        int4 a = __ldg((const int4*)(ei + 2 * e0));
        int4 b = __ldg((const int4*)(ei + 2 * e0) + 1);
        s[0] = a.x; s[1] = a.z; s[2] = b.x; s[3] = b.z;
        int4 c = __ldg((const int4*)(ei + 2 * (size_t)E + 2 * e0));
        int4 f = __ldg((const int4*)(ei + 2 * (size_t)E + 2 * e0) + 1);
        d[0] = c.x; d[1] = c.z; d[2] = f.x; d[3] = f.z;
    } else {
        int4 a = __ldg((const int4*)(ei + e0));
        s[0] = a.x; s[1] = a.y; s[2] = a.z; s[3] = a.w;
        int4 c = __ldg((const int4*)(ei + E + e0));
        d[0] = c.x; d[1] = c.y; d[2] = c.z; d[3] = c.w;
    }
#pragma unroll
    for (int k = 0; k < 4; k++) {
        if (e0 + k < E) {
            int c = atomicAdd(&g_cnt[d[k]], 1);
            if (c < CAP) g_eidx[(d[k] << 7) + c] = s[k];
        }
    }
}

// ---------------------------------------------------------------- GEMM1 (+dis): h1 = (x@W1)*dis, fp16
__global__ void k_gemm1(const float* __restrict__ x, const float* __restrict__ W1, int n) {
    int lane  = threadIdx.x & 31;
    int warp0 = (blockIdx.x * blockDim.x + threadIdx.x) >> 5;
    int nw    = (gridDim.x * blockDim.x) >> 5;

    float w[4][16];
#pragma unroll
    for (int j = 0; j < 4; j++)
#pragma unroll
        for (int c = 0; c < 16; c++) w[j][c] = W1[(lane * 4 + j) * HID + c];

    // value-split butterfly leaves lane L holding channel bitrev4(L&15)
    int cmap = ((lane & 1) << 3) | ((lane & 2) << 1) | ((lane & 4) >> 1) | ((lane & 8) >> 3);

    for (int node = warp0; node < n; node += nw) {
        float4 v = __ldg(((const float4*)(x + (size_t)node * IN_CH)) + lane);
        float acc[16];
#pragma unroll
        for (int c = 0; c < 16; c++)
            acc[c] = v.x * w[0][c] + v.y * w[1][c] + v.z * w[2][c] + v.w * w[3][c];

#pragma unroll
        for (int step = 0; step < 4; step++) {
            int half = 8 >> step;
            bool up = (lane >> step) & 1;
#pragma unroll
            for (int j = 0; j < 8; j++) {
                if (j < half) {
                    float send = up ? acc[j] : acc[j + half];
                    float recv = __shfl_xor_sync(0xffffffffu, send, 1 << step);
                    acc[j] = (up ? acc[j + half] : acc[j]) + recv;
                }
            }
        }
        float tot = acc[0] + __shfl_xor_sync(0xffffffffu, acc[0], 16);
        float dn = rsqrtf((float)(__ldg(&g_cnt[node]) + 1));
        if (lane == 0) g_dis[node] = dn;
        float mine = tot * dn;
        float partner = __shfl_xor_sync(0xffffffffu, mine, 8);
        if (lane < 8) {
            __half2 p = __floats2half2_rn(mine, partner);
            *(__half2*)&g_h1[(size_t)node * HID + cmap] = p;   // cmap even for lane<8
        }
    }
}

// ---------------------------------------------------------------- layer-1 aggregation + ReLU (fp16 rows)
// Warp per node; 4 lanes/edge (uint2 = 4 halves per lane); 8 edge-groups stride-8; unroll 4.
__global__ void k_agg1(const float* __restrict__ b1, int n) {
    int node = (blockIdx.x * blockDim.x + threadIdx.x) >> 5;
    if (node >= n) return;
    int lane = threadIdx.x & 31;
    int j = lane & 3;        // channel quad: 4j..4j+3
    int g = lane >> 2;       // edge group
    int beg = node << 7;
    int end = beg + min(g_cnt[node], CAP);

    float ax = 0.f, ay = 0.f, az = 0.f, aw = 0.f;
    int i = beg + g;
#pragma unroll 1
    for (; i + 24 < end; i += 32) {
        int s0 = __ldg(&g_eidx[i]);
        int s1 = __ldg(&g_eidx[i + 8]);
        int s2 = __ldg(&g_eidx[i + 16]);
        int s3 = __ldg(&g_eidx[i + 24]);
        uint2 r0 = __ldg((const uint2*)(g_h1 + (size_t)s0 * HID) + j);
        uint2 r1 = __ldg((const uint2*)(g_h1 + (size_t)s1 * HID) + j);
        uint2 r2 = __ldg((const uint2*)(g_h1 + (size_t)s2 * HID) + j);
        uint2 r3 = __ldg((const uint2*)(g_h1 + (size_t)s3 * HID) + j);
        float2 f0a = __half22float2(*(__half2*)&r0.x), f0b = __half22float2(*(__half2*)&r0.y);
        float2 f1a = __half22float2(*(__half2*)&r1.x), f1b = __half22float2(*(__half2*)&r1.y);
        float2 f2a = __half22float2(*(__half2*)&r2.x), f2b = __half22float2(*(__half2*)&r2.y);
        float2 f3a = __half22float2(*(__half2*)&r3.x), f3b = __half22float2(*(__half2*)&r3.y);
        ax += (f0a.x + f1a.x) + (f2a.x + f3a.x);
        ay += (f0a.y + f1a.y) + (f2a.y + f3a.y);
        az += (f0b.x + f1b.x) + (f2b.x + f3b.x);
        aw += (f0b.y + f1b.y) + (f2b.y + f3b.y);
    }
    for (; i < end; i += 8) {
        int s0 = __ldg(&g_eidx[i]);
        uint2 r0 = __ldg((const uint2*)(g_h1 + (size_t)s0 * HID) + j);
        float2 f0a = __half22float2(*(__half2*)&r0.x), f0b = __half22float2(*(__half2*)&r0.y);
        ax += f0a.x; ay += f0a.y; az += f0b.x; aw += f0b.y;
    }
#pragma unroll
    for (int m = 4; m <= 16; m <<= 1) {
        ax += __shfl_xor_sync(0xffffffffu, ax, m);
        ay += __shfl_xor_sync(0xffffffffu, ay, m);
        az += __shfl_xor_sync(0xffffffffu, az, m);
        aw += __shfl_xor_sync(0xffffffffu, aw, m);
    }
    if (lane < 4) {
        float dn = g_dis[node];
        uint2 sr = *((const uint2*)(g_h1 + (size_t)node * HID) + j);
        float2 sa = __half22float2(*(__half2*)&sr.x), sb = __half22float2(*(__half2*)&sr.y);
        float4 bb = *(const float4*)&b1[4 * j];
        float ox = fmaxf(dn * (ax + sa.x) + bb.x, 0.0f) * dn;
        float oy = fmaxf(dn * (ay + sa.y) + bb.y, 0.0f) * dn;
        float oz = fmaxf(dn * (az + sb.x) + bb.z, 0.0f) * dn;
        float ow = fmaxf(dn * (aw + sb.y) + bb.w, 0.0f) * dn;
        uint2 o;
        *(__half2*)&o.x = __floats2half2_rn(ox, oy);
        *(__half2*)&o.y = __floats2half2_rn(oz, ow);
        *((uint2*)(g_hr + (size_t)node * HID) + j) = o;
    }
}

// ---------------------------------------------------------------- layer-2 aggregation + W2 -> out (+cnt reset)
__global__ void k_agg2(const float* __restrict__ W2, const float* __restrict__ b2,
                       float* __restrict__ out, int n) {
    int node = (blockIdx.x * blockDim.x + threadIdx.x) >> 5;
    if (node >= n) return;
    int lane = threadIdx.x & 31;
    int j = lane & 3;
    int g = lane >> 2;

    float w2c[16];
#pragma unroll
    for (int c = 0; c < 16; c++) w2c[c] = __ldg(&W2[c * OUT_CH + lane]);
    float bb = __ldg(&b2[lane]);

    int beg = node << 7;
    int end = beg + min(g_cnt[node], CAP);
    float ax = 0.f, ay = 0.f, az = 0.f, aw = 0.f;
    int i = beg + g;
#pragma unroll 1
    for (; i + 24 < end; i += 32) {
        int s0 = __ldg(&g_eidx[i]);
        int s1 = __ldg(&g_eidx[i + 8]);
        int s2 = __ldg(&g_eidx[i + 16]);
        int s3 = __ldg(&g_eidx[i + 24]);
        uint2 r0 = __ldg((const uint2*)(g_hr + (size_t)s0 * HID) + j);
        uint2 r1 = __ldg((const uint2*)(g_hr + (size_t)s1 * HID) + j);
        uint2 r2 = __ldg((const uint2*)(g_hr + (size_t)s2 * HID) + j);
        uint2 r3 = __ldg((const uint2*)(g_hr + (size_t)s3 * HID) + j);
        float2 f0a = __half22float2(*(__half2*)&r0.x), f0b = __half22float2(*(__half2*)&r0.y);
        float2 f1a = __half22float2(*(__half2*)&r1.x), f1b = __half22float2(*(__half2*)&r1.y);
        float2 f2a = __half22float2(*(__half2*)&r2.x), f2b = __half22float2(*(__half2*)&r2.y);
        float2 f3a = __half22float2(*(__half2*)&r3.x), f3b = __half22float2(*(__half2*)&r3.y);
        ax += (f0a.x + f1a.x) + (f2a.x + f3a.x);
        ay += (f0a.y + f1a.y) + (f2a.y + f3a.y);
        az += (f0b.x + f1b.x) + (f2b.x + f3b.x);
        aw += (f0b.y + f1b.y) + (f2b.y + f3b.y);
    }
    for (; i < end; i += 8) {
        int s0 = __ldg(&g_eidx[i]);
        uint2 r0 = __ldg((const uint2*)(g_hr + (size_t)s0 * HID) + j);
        float2 f0a = __half22float2(*(__half2*)&r0.x), f0b = __half22float2(*(__half2*)&r0.y);
        ax += f0a.x; ay += f0a.y; az += f0b.x; aw += f0b.y;
    }
    if (g == 0) {   // add self once, pre-reduction (lanes 0..3)
        uint2 sr = *((const uint2*)(g_hr + (size_t)node * HID) + j);
        float2 sa = __half22float2(*(__half2*)&sr.x), sb = __half22float2(*(__half2*)&sr.y);
        ax += sa.x; ay += sa.y; az += sb.x; aw += sb.y;
    }
#pragma unroll
    for (int m = 4; m <= 16; m <<= 1) {
        ax += __shfl_xor_sync(0xffffffffu, ax, m);
        ay += __shfl_xor_sync(0xffffffffu, ay, m);
        az += __shfl_xor_sync(0xffffffffu, az, m);
        aw += __shfl_xor_sync(0xffffffffu, aw, m);
    }
    float s = 0.0f;
#pragma unroll
    for (int jj = 0; jj < 4; jj++) {
        float tx = __shfl_sync(0xffffffffu, ax, jj);
        float ty = __shfl_sync(0xffffffffu, ay, jj);
        float tz = __shfl_sync(0xffffffffu, az, jj);
        float tw = __shfl_sync(0xffffffffu, aw, jj);
        s = fmaf(tx, w2c[4 * jj + 0], s);
        s = fmaf(ty, w2c[4 * jj + 1], s);
        s = fmaf(tz, w2c[4 * jj + 2], s);
        s = fmaf(tw, w2c[4 * jj + 3], s);
    }
    float dn = g_dis[node];
    out[(size_t)node * OUT_CH + lane] = bb + dn * s;
    if (lane == 0) g_cnt[node] = 0;     // reset for next call
}

// ----------------------------------------------------------------
extern "C" void kernel_launch(void* const* d_in, const int* in_sizes, int n_in,
                              void* d_out, int out_size) {
    const float* x   = (const float*)d_in[0];
    const int*   ei  = (const int*)d_in[1];
    const float* W1  = (const float*)d_in[2];
    const float* b1  = (const float*)d_in[3];
    const float* W2  = (const float*)d_in[4];
    const float* b2  = (const float*)d_in[5];
    float*       out = (float*)d_out;

    const int N = in_sizes[0] / IN_CH;
    const int E = in_sizes[1] / 2;
    const int TB = 256;

    k_fill<<<(E / 4 + TB - 1) / TB, TB>>>(ei, E);           // 1
    k_gemm1<<<1024, TB>>>(x, W1, N);                        // 2
    k_agg1<<<(N * 32 + TB - 1) / TB, TB>>>(b1, N);          // 3
    k_agg2<<<(N * 32 + TB - 1) / TB, TB>>>(W2, b2, out, N); // 4  <- profiled window
}

// round 12
// speedup vs baseline: 1.0472x; 1.0368x over previous
#include <cuda_runtime.h>
#include <cuda_fp16.h>
#include <stdint.h>

#define MAX_NODES 100000
#define IN_CH 128
#define HID 16
#define OUT_CH 32
#define CAP 128

__device__ __align__(16) int    g_cnt[MAX_NODES];          // zero at load; re-zeroed in agg2 epilogue
__device__ __align__(16) float  g_dis[MAX_NODES];
__device__ __align__(16) int    g_eidx[MAX_NODES * CAP];   // ELL: src ids grouped by dst
__device__ __align__(16) __half g_h1[MAX_NODES * HID];     // (x@W1) then *dis[n] after k_scale
__device__ __align__(16) __half g_hr[MAX_NODES * HID];     // relu(dis*agg+b1)*dis[n]

// ---------------------------------------------------------------- ELL fill: 4 edges per thread
__global__ void k_fill(const int* __restrict__ ei, int E) {
    // per-warp dtype sniff on first 128 logical elements' high words (L1 broadcast)
    int lane = threadIdx.x & 31;
    int o = 0;
#pragma unroll
    for (int q = 0; q < 4; q++) o |= __ldg(&ei[2 * (lane * 4 + q) + 1]);
    int is64 = __any_sync(0xffffffffu, o != 0) ? 0 : 1;

    int t = blockIdx.x * blockDim.x + threadIdx.x;
    int e0 = t * 4;
    if (e0 >= E) return;

    int s[4], d[4];
    if (is64) {
        int4 a = __ldg((const int4*)(ei + 2 * e0));
        int4 b = __ldg((const int4*)(ei + 2 * e0) + 1);
        s[0] = a.x; s[1] = a.z; s[2] = b.x; s[3] = b.z;
        int4 c = __ldg((const int4*)(ei + 2 * (size_t)E + 2 * e0));
        int4 f = __ldg((const int4*)(ei + 2 * (size_t)E + 2 * e0) + 1);
        d[0] = c.x; d[1] = c.z; d[2] = f.x; d[3] = f.z;
    } else {
        int4 a = __ldg((const int4*)(ei + e0));
        s[0] = a.x; s[1] = a.y; s[2] = a.z; s[3] = a.w;
        int4 c = __ldg((const int4*)(ei + E + e0));
        d[0] = c.x; d[1] = c.y; d[2] = c.z; d[3] = c.w;
    }
#pragma unroll
    for (int k = 0; k < 4; k++) {
        if (e0 + k < E) {
            int c = atomicAdd(&g_cnt[d[k]], 1);
            if (c < CAP) g_eidx[(d[k] << 7) + c] = s[k];
        }
    }
}

// ---------------------------------------------------------------- matmul only: h1_raw = x@W1 (fp16)
// Runs CONCURRENTLY with k_fill (no dependence on edges/cnt).
__global__ void k_mm(const float* __restrict__ x, const float* __restrict__ W1, int n) {
    int lane  = threadIdx.x & 31;
    int warp0 = (blockIdx.x * blockDim.x + threadIdx.x) >> 5;
    int nw    = (gridDim.x * blockDim.x) >> 5;

    float w[4][16];
#pragma unroll
    for (int j = 0; j < 4; j++)
#pragma unroll
        for (int c = 0; c < 16; c++) w[j][c] = W1[(lane * 4 + j) * HID + c];

    // value-split butterfly leaves lane L holding channel bitrev4(L&15)
    int cmap = ((lane & 1) << 3) | ((lane & 2) << 1) | ((lane & 4) >> 1) | ((lane & 8) >> 3);

    for (int node = warp0; node < n; node += nw) {
        float4 v = __ldg(((const float4*)(x + (size_t)node * IN_CH)) + lane);
        float acc[16];
#pragma unroll
        for (int c = 0; c < 16; c++)
            acc[c] = v.x * w[0][c] + v.y * w[1][c] + v.z * w[2][c] + v.w * w[3][c];

#pragma unroll
        for (int step = 0; step < 4; step++) {
            int half = 8 >> step;
            bool up = (lane >> step) & 1;
#pragma unroll
            for (int j = 0; j < 8; j++) {
                if (j < half) {
                    float send = up ? acc[j] : acc[j + half];
                    float recv = __shfl_xor_sync(0xffffffffu, send, 1 << step);
                    acc[j] = (up ? acc[j + half] : acc[j]) + recv;
                }
            }
        }
        float tot = acc[0] + __shfl_xor_sync(0xffffffffu, acc[0], 16);
        float partner = __shfl_xor_sync(0xffffffffu, tot, 8);
        if (lane < 8) {
            __half2 p = __floats2half2_rn(tot, partner);
            *(__half2*)&g_h1[(size_t)node * HID + cmap] = p;   // cmap even for lane<8
        }
    }
}

// ---------------------------------------------------------------- scale: dis = rsqrt(cnt+1); h1 *= dis
__global__ void k_scale(int n) {
    int node = blockIdx.x * blockDim.x + threadIdx.x;
    if (node >= n) return;
    float dn = rsqrtf((float)(g_cnt[node] + 1));
    g_dis[node] = dn;
    uint4* row = (uint4*)&g_h1[(size_t)node * HID];
#pragma unroll
    for (int half = 0; half < 2; half++) {
        uint4 r = row[half];
        __half2* h = (__half2*)&r;
#pragma unroll
        for (int k = 0; k < 4; k++) {
            float2 f = __half22float2(h[k]);
            h[k] = __floats2half2_rn(f.x * dn, f.y * dn);
        }
        row[half] = r;
    }
}

// ---------------------------------------------------------------- layer-1 aggregation + ReLU (fp16 rows)
// Warp per node; 4 lanes/edge (uint2/lane); 8 edge-groups stride-8; unroll 4.
__global__ void k_agg1(const float* __restrict__ b1, int n) {
    int node = (blockIdx.x * blockDim.x + threadIdx.x) >> 5;
    if (node >= n) return;
    int lane = threadIdx.x & 31;
    int j = lane & 3;        // channel quad: 4j..4j+3
    int g = lane >> 2;       // edge group
    int beg = node << 7;
    int end = beg + min(g_cnt[node], CAP);

    float ax = 0.f, ay = 0.f, az = 0.f, aw = 0.f;
    int i = beg + g;
#pragma unroll 1
    for (; i + 24 < end; i += 32) {
        int s0 = __ldg(&g_eidx[i]);
        int s1 = __ldg(&g_eidx[i + 8]);
        int s2 = __ldg(&g_eidx[i + 16]);
        int s3 = __ldg(&g_eidx[i + 24]);
        uint2 r0 = __ldg((const uint2*)(g_h1 + (size_t)s0 * HID) + j);
        uint2 r1 = __ldg((const uint2*)(g_h1 + (size_t)s1 * HID) + j);
        uint2 r2 = __ldg((const uint2*)(g_h1 + (size_t)s2 * HID) + j);
        uint2 r3 = __ldg((const uint2*)(g_h1 + (size_t)s3 * HID) + j);
        float2 f0a = __half22float2(*(__half2*)&r0.x), f0b = __half22float2(*(__half2*)&r0.y);
        float2 f1a = __half22float2(*(__half2*)&r1.x), f1b = __half22float2(*(__half2*)&r1.y);
        float2 f2a = __half22float2(*(__half2*)&r2.x), f2b = __half22float2(*(__half2*)&r2.y);
        float2 f3a = __half22float2(*(__half2*)&r3.x), f3b = __half22float2(*(__half2*)&r3.y);
        ax += (f0a.x + f1a.x) + (f2a.x + f3a.x);
        ay += (f0a.y + f1a.y) + (f2a.y + f3a.y);
        az += (f0b.x + f1b.x) + (f2b.x + f3b.x);
        aw += (f0b.y + f1b.y) + (f2b.y + f3b.y);
    }
    for (; i < end; i += 8) {
        int s0 = __ldg(&g_eidx[i]);
        uint2 r0 = __ldg((const uint2*)(g_h1 + (size_t)s0 * HID) + j);
        float2 f0a = __half22float2(*(__half2*)&r0.x), f0b = __half22float2(*(__half2*)&r0.y);
        ax += f0a.x; ay += f0a.y; az += f0b.x; aw += f0b.y;
    }
#pragma unroll
    for (int m = 4; m <= 16; m <<= 1) {
        ax += __shfl_xor_sync(0xffffffffu, ax, m);
        ay += __shfl_xor_sync(0xffffffffu, ay, m);
        az += __shfl_xor_sync(0xffffffffu, az, m);
        aw += __shfl_xor_sync(0xffffffffu, aw, m);
    }
    if (lane < 4) {
        float dn = g_dis[node];
        uint2 sr = *((const uint2*)(g_h1 + (size_t)node * HID) + j);
        float2 sa = __half22float2(*(__half2*)&sr.x), sb = __half22float2(*(__half2*)&sr.y);
        float4 bb = *(const float4*)&b1[4 * j];
        float ox = fmaxf(dn * (ax + sa.x) + bb.x, 0.0f) * dn;
        float oy = fmaxf(dn * (ay + sa.y) + bb.y, 0.0f) * dn;
        float oz = fmaxf(dn * (az + sb.x) + bb.z, 0.0f) * dn;
        float ow = fmaxf(dn * (aw + sb.y) + bb.w, 0.0f) * dn;
        uint2 o;
        *(__half2*)&o.x = __floats2half2_rn(ox, oy);
        *(__half2*)&o.y = __floats2half2_rn(oz, ow);
        *((uint2*)(g_hr + (size_t)node * HID) + j) = o;
    }
}

// ---------------------------------------------------------------- layer-2 aggregation + W2 -> out (+cnt reset)
__global__ void k_agg2(const float* __restrict__ W2, const float* __restrict__ b2,
                       float* __restrict__ out, int n) {
    int node = (blockIdx.x * blockDim.x + threadIdx.x) >> 5;
    if (node >= n) return;
    int lane = threadIdx.x & 31;
    int j = lane & 3;
    int g = lane >> 2;

    float w2c[16];
#pragma unroll
    for (int c = 0; c < 16; c++) w2c[c] = __ldg(&W2[c * OUT_CH + lane]);
    float bb = __ldg(&b2[lane]);

    int beg = node << 7;
    int end = beg + min(g_cnt[node], CAP);
    float ax = 0.f, ay = 0.f, az = 0.f, aw = 0.f;
    int i = beg + g;
#pragma unroll 1
    for (; i + 24 < end; i += 32) {
        int s0 = __ldg(&g_eidx[i]);
        int s1 = __ldg(&g_eidx[i + 8]);
        int s2 = __ldg(&g_eidx[i + 16]);
        int s3 = __ldg(&g_eidx[i + 24]);
        uint2 r0 = __ldg((const uint2*)(g_hr + (size_t)s0 * HID) + j);
        uint2 r1 = __ldg((const uint2*)(g_hr + (size_t)s1 * HID) + j);
        uint2 r2 = __ldg((const uint2*)(g_hr + (size_t)s2 * HID) + j);
        uint2 r3 = __ldg((const uint2*)(g_hr + (size_t)s3 * HID) + j);
        float2 f0a = __half22float2(*(__half2*)&r0.x), f0b = __half22float2(*(__half2*)&r0.y);
        float2 f1a = __half22float2(*(__half2*)&r1.x), f1b = __half22float2(*(__half2*)&r1.y);
        float2 f2a = __half22float2(*(__half2*)&r2.x), f2b = __half22float2(*(__half2*)&r2.y);
        float2 f3a = __half22float2(*(__half2*)&r3.x), f3b = __half22float2(*(__half2*)&r3.y);
        ax += (f0a.x + f1a.x) + (f2a.x + f3a.x);
        ay += (f0a.y + f1a.y) + (f2a.y + f3a.y);
        az += (f0b.x + f1b.x) + (f2b.x + f3b.x);
        aw += (f0b.y + f1b.y) + (f2b.y + f3b.y);
    }
    for (; i < end; i += 8) {
        int s0 = __ldg(&g_eidx[i]);
        uint2 r0 = __ldg((const uint2*)(g_hr + (size_t)s0 * HID) + j);
        float2 f0a = __half22float2(*(__half2*)&r0.x), f0b = __half22float2(*(__half2*)&r0.y);
        ax += f0a.x; ay += f0a.y; az += f0b.x; aw += f0b.y;
    }
    if (g == 0) {   // add self once, pre-reduction (lanes 0..3)
        uint2 sr = *((const uint2*)(g_hr + (size_t)node * HID) + j);
        float2 sa = __half22float2(*(__half2*)&sr.x), sb = __half22float2(*(__half2*)&sr.y);
        ax += sa.x; ay += sa.y; az += sb.x; aw += sb.y;
    }
#pragma unroll
    for (int m = 4; m <= 16; m <<= 1) {
        ax += __shfl_xor_sync(0xffffffffu, ax, m);
        ay += __shfl_xor_sync(0xffffffffu, ay, m);
        az += __shfl_xor_sync(0xffffffffu, az, m);
        aw += __shfl_xor_sync(0xffffffffu, aw, m);
    }
    float s = 0.0f;
#pragma unroll
    for (int jj = 0; jj < 4; jj++) {
        float tx = __shfl_sync(0xffffffffu, ax, jj);
        float ty = __shfl_sync(0xffffffffu, ay, jj);
        float tz = __shfl_sync(0xffffffffu, az, jj);
        float tw = __shfl_sync(0xffffffffu, aw, jj);
        s = fmaf(tx, w2c[4 * jj + 0], s);
        s = fmaf(ty, w2c[4 * jj + 1], s);
        s = fmaf(tz, w2c[4 * jj + 2], s);
        s = fmaf(tw, w2c[4 * jj + 3], s);
    }
    float dn = g_dis[node];
    out[(size_t)node * OUT_CH + lane] = bb + dn * s;
    if (lane == 0) g_cnt[node] = 0;     // reset for next call
}

// ----------------------------------------------------------------
extern "C" void kernel_launch(void* const* d_in, const int* in_sizes, int n_in,
                              void* d_out, int out_size) {
    const float* x   = (const float*)d_in[0];
    const int*   ei  = (const int*)d_in[1];
    const float* W1  = (const float*)d_in[2];
    const float* b1  = (const float*)d_in[3];
    const float* W2  = (const float*)d_in[4];
    const float* b2  = (const float*)d_in[5];
    float*       out = (float*)d_out;

    const int N = in_sizes[0] / IN_CH;
    const int E = in_sizes[1] / 2;
    const int TB = 256;

    // One-time infra (created on the first, non-captured correctness call).
    static cudaStream_t s2 = nullptr;
    static cudaEvent_t ev_fork = nullptr, ev_join = nullptr;
    if (s2 == nullptr) {
        cudaStreamCreateWithFlags(&s2, cudaStreamNonBlocking);
        cudaEventCreateWithFlags(&ev_fork, cudaEventDisableTiming);
        cudaEventCreateWithFlags(&ev_join, cudaEventDisableTiming);
    }

    // Fork: k_mm (independent of edges) runs concurrently with k_fill.
    cudaEventRecord(ev_fork, 0);
    cudaStreamWaitEvent(s2, ev_fork, 0);
    k_mm<<<1024, TB, 0, s2>>>(x, W1, N);                    // side branch
    cudaEventRecord(ev_join, s2);

    k_fill<<<(E / 4 + TB - 1) / TB, TB>>>(ei, E);           // main branch
    cudaStreamWaitEvent(0, ev_join, 0);                     // join

    k_scale<<<(N + TB - 1) / TB, TB>>>(N);
    k_agg1<<<(N * 32 + TB - 1) / TB, TB>>>(b1, N);          // launch #4 in window
    k_agg2<<<(N * 32 + TB - 1) / TB, TB>>>(W2, b2, out, N);
}

// round 13
// speedup vs baseline: 1.0678x; 1.0198x over previous
#include <cuda_runtime.h>
#include <cuda_fp16.h>
#include <stdint.h>

#define MAX_NODES 100000
#define IN_CH 128
#define HID 16
#define OUT_CH 32
#define CAP 128

__device__ __align__(16) int    g_cnt[MAX_NODES];          // zero at load; re-zeroed in agg2 epilogue
__device__ __align__(16) float  g_dis[MAX_NODES];
__device__ __align__(16) int    g_eidx[MAX_NODES * CAP];   // ELL: src ids grouped by dst
__device__ __align__(16) __half g_h1[MAX_NODES * HID];     // (x@W1) then *dis[n] after k_scale
__device__ __align__(16) __half g_hr[MAX_NODES * HID];     // relu(dis*agg+b1)*dis[n]

// ---------------------------------------------------------------- ELL fill: 4 edges per thread
__global__ void k_fill(const int* __restrict__ ei, int E) {
    // per-warp dtype sniff on first 128 logical elements' high words (L1 broadcast)
    int lane = threadIdx.x & 31;
    int o = 0;
#pragma unroll
    for (int q = 0; q < 4; q++) o |= __ldg(&ei[2 * (lane * 4 + q) + 1]);
    int is64 = __any_sync(0xffffffffu, o != 0) ? 0 : 1;

    int t = blockIdx.x * blockDim.x + threadIdx.x;
    int e0 = t * 4;
    if (e0 >= E) return;

    int s[4], d[4];
    if (is64) {
        int4 a = __ldg((const int4*)(ei + 2 * e0));
        int4 b = __ldg((const int4*)(ei + 2 * e0) + 1);
        s[0] = a.x; s[1] = a.z; s[2] = b.x; s[3] = b.z;
        int4 c = __ldg((const int4*)(ei + 2 * (size_t)E + 2 * e0));
        int4 f = __ldg((const int4*)(ei + 2 * (size_t)E + 2 * e0) + 1);
        d[0] = c.x; d[1] = c.z; d[2] = f.x; d[3] = f.z;
    } else {
        int4 a = __ldg((const int4*)(ei + e0));
        s[0] = a.x; s[1] = a.y; s[2] = a.z; s[3] = a.w;
        int4 c = __ldg((const int4*)(ei + E + e0));
        d[0] = c.x; d[1] = c.y; d[2] = c.z; d[3] = c.w;
    }
#pragma unroll
    for (int k = 0; k < 4; k++) {
        if (e0 + k < E) {
            int c = atomicAdd(&g_cnt[d[k]], 1);
            if (c < CAP) g_eidx[(d[k] << 7) + c] = s[k];
        }
    }
}

// ---------------------------------------------------------------- matmul only: h1_raw = x@W1 (fp16)
// Runs CONCURRENTLY with k_fill (no dependence on edges/cnt).
__global__ void k_mm(const float* __restrict__ x, const float* __restrict__ W1, int n) {
    int lane  = threadIdx.x & 31;
    int warp0 = (blockIdx.x * blockDim.x + threadIdx.x) >> 5;
    int nw    = (gridDim.x * blockDim.x) >> 5;

    float w[4][16];
#pragma unroll
    for (int j = 0; j < 4; j++)
#pragma unroll
        for (int c = 0; c < 16; c++) w[j][c] = W1[(lane * 4 + j) * HID + c];

    // value-split butterfly leaves lane L holding channel bitrev4(L&15)
    int cmap = ((lane & 1) << 3) | ((lane & 2) << 1) | ((lane & 4) >> 1) | ((lane & 8) >> 3);

    for (int node = warp0; node < n; node += nw) {
        float4 v = __ldg(((const float4*)(x + (size_t)node * IN_CH)) + lane);
        float acc[16];
#pragma unroll
        for (int c = 0; c < 16; c++)
            acc[c] = v.x * w[0][c] + v.y * w[1][c] + v.z * w[2][c] + v.w * w[3][c];

#pragma unroll
        for (int step = 0; step < 4; step++) {
            int half = 8 >> step;
            bool up = (lane >> step) & 1;
#pragma unroll
            for (int j = 0; j < 8; j++) {
                if (j < half) {
                    float send = up ? acc[j] : acc[j + half];
                    float recv = __shfl_xor_sync(0xffffffffu, send, 1 << step);
                    acc[j] = (up ? acc[j + half] : acc[j]) + recv;
                }
            }
        }
        float tot = acc[0] + __shfl_xor_sync(0xffffffffu, acc[0], 16);
        float partner = __shfl_xor_sync(0xffffffffu, tot, 8);
        if (lane < 8) {
            __half2 p = __floats2half2_rn(tot, partner);
            *(__half2*)&g_h1[(size_t)node * HID + cmap] = p;   // cmap even for lane<8
        }
    }
}

// ---------------------------------------------------------------- scale: dis = rsqrt(cnt+1); h1 *= dis
__global__ void k_scale(int n) {
    int node = blockIdx.x * blockDim.x + threadIdx.x;
    if (node >= n) return;
    float dn = rsqrtf((float)(g_cnt[node] + 1));
    g_dis[node] = dn;
    uint4* row = (uint4*)&g_h1[(size_t)node * HID];
#pragma unroll
    for (int half = 0; half < 2; half++) {
        uint4 r = row[half];
        __half2* h = (__half2*)&r;
#pragma unroll
        for (int k = 0; k < 4; k++) {
            float2 f = __half22float2(h[k]);
            h[k] = __floats2half2_rn(f.x * dn, f.y * dn);
        }
        row[half] = r;
    }
}

// ---------------------------------------------------------------- layer-1 aggregation + ReLU (fp16 rows)
// Warp per node; 4 lanes/edge (uint2/lane); 8 edge-groups stride-8; unroll 4.
__global__ void k_agg1(const float* __restrict__ b1, int n) {
    int node = (blockIdx.x * blockDim.x + threadIdx.x) >> 5;
    if (node >= n) return;
    int lane = threadIdx.x & 31;
    int j = lane & 3;        // channel quad: 4j..4j+3
    int g = lane >> 2;       // edge group
    int beg = node << 7;
    int end = beg + min(g_cnt[node], CAP);

    float ax = 0.f, ay = 0.f, az = 0.f, aw = 0.f;
    int i = beg + g;
#pragma unroll 1
    for (; i + 24 < end; i += 32) {
        int s0 = __ldg(&g_eidx[i]);
        int s1 = __ldg(&g_eidx[i + 8]);
        int s2 = __ldg(&g_eidx[i + 16]);
        int s3 = __ldg(&g_eidx[i + 24]);
        uint2 r0 = __ldg((const uint2*)(g_h1 + (size_t)s0 * HID) + j);
        uint2 r1 = __ldg((const uint2*)(g_h1 + (size_t)s1 * HID) + j);
        uint2 r2 = __ldg((const uint2*)(g_h1 + (size_t)s2 * HID) + j);
        uint2 r3 = __ldg((const uint2*)(g_h1 + (size_t)s3 * HID) + j);
        float2 f0a = __half22float2(*(__half2*)&r0.x), f0b = __half22float2(*(__half2*)&r0.y);
        float2 f1a = __half22float2(*(__half2*)&r1.x), f1b = __half22float2(*(__half2*)&r1.y);
        float2 f2a = __half22float2(*(__half2*)&r2.x), f2b = __half22float2(*(__half2*)&r2.y);
        float2 f3a = __half22float2(*(__half2*)&r3.x), f3b = __half22float2(*(__half2*)&r3.y);
        ax += (f0a.x + f1a.x) + (f2a.x + f3a.x);
        ay += (f0a.y + f1a.y) + (f2a.y + f3a.y);
        az += (f0b.x + f1b.x) + (f2b.x + f3b.x);
        aw += (f0b.y + f1b.y) + (f2b.y + f3b.y);
    }
    for (; i < end; i += 8) {
        int s0 = __ldg(&g_eidx[i]);
        uint2 r0 = __ldg((const uint2*)(g_h1 + (size_t)s0 * HID) + j);
        float2 f0a = __half22float2(*(__half2*)&r0.x), f0b = __half22float2(*(__half2*)&r0.y);
        ax += f0a.x; ay += f0a.y; az += f0b.x; aw += f0b.y;
    }
#pragma unroll
    for (int m = 4; m <= 16; m <<= 1) {
        ax += __shfl_xor_sync(0xffffffffu, ax, m);
        ay += __shfl_xor_sync(0xffffffffu, ay, m);
        az += __shfl_xor_sync(0xffffffffu, az, m);
        aw += __shfl_xor_sync(0xffffffffu, aw, m);
    }
    if (lane < 4) {
        float dn = g_dis[node];
        uint2 sr = *((const uint2*)(g_h1 + (size_t)node * HID) + j);
        float2 sa = __half22float2(*(__half2*)&sr.x), sb = __half22float2(*(__half2*)&sr.y);
        float4 bb = *(const float4*)&b1[4 * j];
        float ox = fmaxf(dn * (ax + sa.x) + bb.x, 0.0f) * dn;
        float oy = fmaxf(dn * (ay + sa.y) + bb.y, 0.0f) * dn;
        float oz = fmaxf(dn * (az + sb.x) + bb.z, 0.0f) * dn;
        float ow = fmaxf(dn * (aw + sb.y) + bb.w, 0.0f) * dn;
        uint2 o;
        *(__half2*)&o.x = __floats2half2_rn(ox, oy);
        *(__half2*)&o.y = __floats2half2_rn(oz, ow);
        *((uint2*)(g_hr + (size_t)node * HID) + j) = o;
    }
}

// ---------------------------------------------------------------- layer-2 aggregation + W2 -> out (+cnt reset)
// W2/b2 staged in shared memory (frees 17 regs -> occupancy like agg1).
__global__ void k_agg2(const float* __restrict__ W2, const float* __restrict__ b2,
                       float* __restrict__ out, int n) {
    __shared__ float s_w2[16 * 32];
    __shared__ float s_b2[32];
    for (int t = threadIdx.x; t < 16 * 32; t += blockDim.x) s_w2[t] = W2[t];
    if (threadIdx.x < 32) s_b2[threadIdx.x] = b2[threadIdx.x];
    __syncthreads();

    int node = (blockIdx.x * blockDim.x + threadIdx.x) >> 5;
    if (node >= n) return;
    int lane = threadIdx.x & 31;
    int j = lane & 3;
    int g = lane >> 2;

    int beg = node << 7;
    int end = beg + min(g_cnt[node], CAP);
    float ax = 0.f, ay = 0.f, az = 0.f, aw = 0.f;
    int i = beg + g;
#pragma unroll 1
    for (; i + 24 < end; i += 32) {
        int s0 = __ldg(&g_eidx[i]);
        int s1 = __ldg(&g_eidx[i + 8]);
        int s2 = __ldg(&g_eidx[i + 16]);
        int s3 = __ldg(&g_eidx[i + 24]);
        uint2 r0 = __ldg((const uint2*)(g_hr + (size_t)s0 * HID) + j);
        uint2 r1 = __ldg((const uint2*)(g_hr + (size_t)s1 * HID) + j);
        uint2 r2 = __ldg((const uint2*)(g_hr + (size_t)s2 * HID) + j);
        uint2 r3 = __ldg((const uint2*)(g_hr + (size_t)s3 * HID) + j);
        float2 f0a = __half22float2(*(__half2*)&r0.x), f0b = __half22float2(*(__half2*)&r0.y);
        float2 f1a = __half22float2(*(__half2*)&r1.x), f1b = __half22float2(*(__half2*)&r1.y);
        float2 f2a = __half22float2(*(__half2*)&r2.x), f2b = __half22float2(*(__half2*)&r2.y);
        float2 f3a = __half22float2(*(__half2*)&r3.x), f3b = __half22float2(*(__half2*)&r3.y);
        ax += (f0a.x + f1a.x) + (f2a.x + f3a.x);
        ay += (f0a.y + f1a.y) + (f2a.y + f3a.y);
        az += (f0b.x + f1b.x) + (f2b.x + f3b.x);
        aw += (f0b.y + f1b.y) + (f2b.y + f3b.y);
    }
    for (; i < end; i += 8) {
        int s0 = __ldg(&g_eidx[i]);
        uint2 r0 = __ldg((const uint2*)(g_hr + (size_t)s0 * HID) + j);
        float2 f0a = __half22float2(*(__half2*)&r0.x), f0b = __half22float2(*(__half2*)&r0.y);
        ax += f0a.x; ay += f0a.y; az += f0b.x; aw += f0b.y;
    }
    if (g == 0) {   // add self once, pre-reduction (lanes 0..3)
        uint2 sr = *((const uint2*)(g_hr + (size_t)node * HID) + j);
        float2 sa = __half22float2(*(__half2*)&sr.x), sb = __half22float2(*(__half2*)&sr.y);
        ax += sa.x; ay += sa.y; az += sb.x; aw += sb.y;
    }
#pragma unroll
    for (int m = 4; m <= 16; m <<= 1) {
        ax += __shfl_xor_sync(0xffffffffu, ax, m);
        ay += __shfl_xor_sync(0xffffffffu, ay, m);
        az += __shfl_xor_sync(0xffffffffu, az, m);
        aw += __shfl_xor_sync(0xffffffffu, aw, m);
    }
    float s = 0.0f;
#pragma unroll
    for (int jj = 0; jj < 4; jj++) {
        float tx = __shfl_sync(0xffffffffu, ax, jj);
        float ty = __shfl_sync(0xffffffffu, ay, jj);
        float tz = __shfl_sync(0xffffffffu, az, jj);
        float tw = __shfl_sync(0xffffffffu, aw, jj);
        s = fmaf(tx, s_w2[(4 * jj + 0) * 32 + lane], s);
        s = fmaf(ty, s_w2[(4 * jj + 1) * 32 + lane], s);
        s = fmaf(tz, s_w2[(4 * jj + 2) * 32 + lane], s);
        s = fmaf(tw, s_w2[(4 * jj + 3) * 32 + lane], s);
    }
    float dn = g_dis[node];
    out[(size_t)node * OUT_CH + lane] = s_b2[lane] + dn * s;
    if (lane == 0) g_cnt[node] = 0;     // reset for next call
}

// ----------------------------------------------------------------
extern "C" void kernel_launch(void* const* d_in, const int* in_sizes, int n_in,
                              void* d_out, int out_size) {
    const float* x   = (const float*)d_in[0];
    const int*   ei  = (const int*)d_in[1];
    const float* W1  = (const float*)d_in[2];
    const float* b1  = (const float*)d_in[3];
    const float* W2  = (const float*)d_in[4];
    const float* b2  = (const float*)d_in[5];
    float*       out = (float*)d_out;

    const int N = in_sizes[0] / IN_CH;
    const int E = in_sizes[1] / 2;
    const int TB = 256;

    // One-time infra (created on the first, non-captured correctness call).
    static cudaStream_t s2 = nullptr;
    static cudaEvent_t ev_fork = nullptr, ev_join = nullptr;
    if (s2 == nullptr) {
        cudaStreamCreateWithFlags(&s2, cudaStreamNonBlocking);
        cudaEventCreateWithFlags(&ev_fork, cudaEventDisableTiming);
        cudaEventCreateWithFlags(&ev_join, cudaEventDisableTiming);
    }

    // Fork: k_mm (independent of edges) runs concurrently with k_fill.
    cudaEventRecord(ev_fork, 0);
    cudaStreamWaitEvent(s2, ev_fork, 0);
    k_mm<<<1024, TB, 0, s2>>>(x, W1, N);                    // side branch
    cudaEventRecord(ev_join, s2);

    k_fill<<<(E / 4 + TB - 1) / TB, TB>>>(ei, E);           // main branch
    cudaStreamWaitEvent(0, ev_join, 0);                     // join

    k_scale<<<(N + TB - 1) / TB, TB>>>(N);
    k_agg1<<<(N * 32 + TB - 1) / TB, TB>>>(b1, N);
    k_agg2<<<(N * 32 + TB - 1) / TB, TB>>>(W2, b2, out, N);
}